// round 8
// baseline (speedup 1.0000x reference)
#include <cuda_runtime.h>
#include <cstdint>

#define NHEAD 16
#define QLEN  4096
#define KLEN  4096
#define DIM   64
#define BQ    128
#define BK    64
#define NTHREADS 128
#define NITER (KLEN / BK)

#define KSS 68   // K tile stride: B-frag bank = 4g+b (conflict-free)
#define VSS 72   // V tile stride: B-frag bank = 8b+g (conflict-free)
#define PST 132  // P pad row stride (transposed [col][row]): bank = 4b+g / 8b+g (CF)

// float offsets in dynamic smem
#define KST0 0
#define KST1 (64 * KSS)                 // 4352
#define VOFF (2 * 64 * KSS)             // 8704
#define POFF (VOFF + 64 * VSS)          // 13312
#define SMEM_FLOATS (POFF + 16 * PST)   // 15424
#define SMEM_BYTES  (SMEM_FLOATS * 4)   // 61696

// pre-rounded tf32 K/V scratch (static __device__: allocation-free)
__device__ uint32_t g_Kr[NHEAD * KLEN * DIM];
__device__ uint32_t g_Vr[NHEAD * KLEN * DIM];

__device__ __forceinline__ uint32_t f2tf(float x) {
    uint32_t r; asm("cvt.rna.tf32.f32 %0, %1;" : "=r"(r) : "f"(x)); return r;
}
__device__ __forceinline__ float fast_exp2(float x) {
    float y; asm("ex2.approx.ftz.f32 %0, %1;" : "=f"(y) : "f"(x)); return y;
}
__device__ __forceinline__ uint32_t smem_u32(const void* p) {
    uint32_t a;
    asm("{ .reg .u64 t; cvta.to.shared.u64 t, %1; cvt.u32.u64 %0, t; }" : "=r"(a) : "l"(p));
    return a;
}
__device__ __forceinline__ void cp16(uint32_t dst, const void* src) {
    asm volatile("cp.async.ca.shared.global [%0], [%1], 16;" :: "r"(dst), "l"(src) : "memory");
}
#define CP_COMMIT() asm volatile("cp.async.commit_group;" ::: "memory")
#define CP_WAIT1()  asm volatile("cp.async.wait_group 1;" ::: "memory")

// D(16x8,f32) += A(16x8,tf32) * B(8x8,tf32)   [row.col]
__device__ __forceinline__ void mma_tf32(float* d, const uint32_t* a,
                                         uint32_t b0, uint32_t b1) {
    asm volatile(
        "mma.sync.aligned.m16n8k8.row.col.f32.tf32.tf32.f32 "
        "{%0,%1,%2,%3}, {%4,%5,%6,%7}, {%8,%9}, {%0,%1,%2,%3};"
        : "+f"(d[0]), "+f"(d[1]), "+f"(d[2]), "+f"(d[3])
        : "r"(a[0]), "r"(a[1]), "r"(a[2]), "r"(a[3]), "r"(b0), "r"(b1));
}

// ---- prepass: round K,V to tf32 (rna) once ----
extern "C" __global__ void __launch_bounds__(256)
kv_round(const float* __restrict__ ks, const float* __restrict__ vs)
{
    const size_t i = (size_t)blockIdx.x * blockDim.x + threadIdx.x;
    float4 k = ((const float4*)ks)[i];
    ((uint4*)g_Kr)[i] = make_uint4(f2tf(k.x), f2tf(k.y), f2tf(k.z), f2tf(k.w));
    float4 v = ((const float4*)vs)[i];
    ((uint4*)g_Vr)[i] = make_uint4(f2tf(v.x), f2tf(v.y), f2tf(v.z), f2tf(v.w));
}

extern "C" __global__ void __launch_bounds__(NTHREADS, 3)
fa_hmma_q4(const float* __restrict__ qs, const unsigned int* __restrict__ maskw,
           float* __restrict__ out)
{
    extern __shared__ float sm[];
    const uint32_t sb = smem_u32(sm);

    const int tid  = threadIdx.x;
    const int w    = tid >> 5;
    const int lane = tid & 31;
    const int g    = lane >> 2;   // row within 8
    const int b    = lane & 3;    // k/col selector

    uint32_t* PPU = (uint32_t*)(sm + POFF);       // P pad, transposed [16 cols][PST]
    const int prow = w * 32 + g;                  // this thread's base P row

    const int head = blockIdx.y;
    const int q0   = blockIdx.x * BQ;
    const int r0   = w * 32 + g;                  // q rows r0, +8, +16, +24

    const float qscale = 0.125f * 1.44269504088896340736f;  // 1/sqrt(D)*log2(e)
    const float* qg = qs + ((size_t)head * QLEN + q0) * DIM;
    const uint32_t* kg = g_Kr + (size_t)head * KLEN * DIM;
    const uint32_t* vg = g_Vr + (size_t)head * KLEN * DIM;

    const int srow = tid >> 4;          // cp.async row base (0..7)
    const int scol = (tid & 15) * 4;    // cp.async col (floats)

    // ---- prologue: issue K(0) -> stage0, V(0), K(1) -> stage1 ----
    #pragma unroll
    for (int i = 0; i < 8; i++) {
        const int r = srow + 8 * i;
        cp16(sb + (KST0 + r * KSS + scol) * 4, kg + (size_t)r * DIM + scol);
    }
    CP_COMMIT();
    #pragma unroll
    for (int i = 0; i < 8; i++) {
        const int r = srow + 8 * i;
        cp16(sb + (VOFF + r * VSS + scol) * 4, vg + (size_t)r * DIM + scol);
    }
    CP_COMMIT();
    #pragma unroll
    for (int i = 0; i < 8; i++) {
        const int r = srow + 8 * i;
        cp16(sb + (KST1 + r * KSS + scol) * 4, kg + (size_t)(BK + r) * DIM + scol);
    }
    CP_COMMIT();

    // ---- persistent Q A-fragments (loaded while cp.async flies) ----
    uint32_t qa[8][8];
    {
        const float* q0p = qg + (size_t)r0 * DIM;
        const float* q1p = q0p + 8 * DIM;
        const float* q2p = q0p + 16 * DIM;
        const float* q3p = q0p + 24 * DIM;
        #pragma unroll
        for (int c = 0; c < 8; c++) {
            const int k0c = c * 8 + b;
            qa[c][0] = f2tf(q0p[k0c]     * qscale);
            qa[c][1] = f2tf(q1p[k0c]     * qscale);
            qa[c][2] = f2tf(q0p[k0c + 4] * qscale);
            qa[c][3] = f2tf(q1p[k0c + 4] * qscale);
            qa[c][4] = f2tf(q2p[k0c]     * qscale);
            qa[c][5] = f2tf(q3p[k0c]     * qscale);
            qa[c][6] = f2tf(q2p[k0c + 4] * qscale);
            qa[c][7] = f2tf(q3p[k0c + 4] * qscale);
        }
    }

    float o[8][8];
    #pragma unroll
    for (int j = 0; j < 8; j++)
        #pragma unroll
        for (int e = 0; e < 8; e++) o[j][e] = 0.0f;
    float mrun[4] = {-1e30f, -1e30f, -1e30f, -1e30f};
    float lrun[4] = {0.0f, 0.0f, 0.0f, 0.0f};

    for (int it = 0; it < NITER; it++) {
        const int k0 = it * BK;
        const int kb = k0 >> 2;

        // groups in flight (oldest first): V(it), K(it+1). Wait for V(it)
        // (and implicitly everything older); K(it+1) may still fly.
        CP_WAIT1();
        __syncthreads();

        const uint32_t* KsU = (const uint32_t*)(sm + ((it & 1) ? KST1 : KST0));
        const uint32_t* VsU = (const uint32_t*)(sm + VOFF);

        // ---- four 16-key quarters ----
        #pragma unroll
        for (int q = 0; q < 4; q++) {
            // MMA1 quarter: S cols q*16..q*16+15
            float sacc[2][8];
            #pragma unroll
            for (int jq = 0; jq < 2; jq++)
                #pragma unroll
                for (int e = 0; e < 8; e++) sacc[jq][e] = 0.0f;

            #pragma unroll
            for (int c = 0; c < 8; c++) {
                #pragma unroll
                for (int jq = 0; jq < 2; jq++) {
                    const int j = q * 2 + jq;
                    const uint32_t* kp = &KsU[(j * 8 + g) * KSS + c * 8 + b];
                    const uint32_t kb0 = kp[0], kb1 = kp[4];
                    mma_tf32(&sacc[jq][0], &qa[c][0], kb0, kb1);
                    mma_tf32(&sacc[jq][4], &qa[c][4], kb0, kb1);
                }
            }

            // mask (robust word-of-4; all-true -> never taken)
            #pragma unroll
            for (int jq = 0; jq < 2; jq++) {
                if (maskw[kb + 2 * (q * 2 + jq) + (b >> 1)] == 0u) {
                    #pragma unroll
                    for (int e = 0; e < 8; e++) sacc[jq][e] = -1e30f;
                }
            }

            // online softmax (log2 domain) over this quarter
            float m[4] = {-1e30f, -1e30f, -1e30f, -1e30f};
            #pragma unroll
            for (int jq = 0; jq < 2; jq++)
                #pragma unroll
                for (int i = 0; i < 4; i++)
                    m[i] = fmaxf(m[i], fmaxf(sacc[jq][2 * i], sacc[jq][2 * i + 1]));
            #pragma unroll
            for (int i = 0; i < 4; i++) {
                m[i] = fmaxf(m[i], __shfl_xor_sync(0xffffffffu, m[i], 1));
                m[i] = fmaxf(m[i], __shfl_xor_sync(0xffffffffu, m[i], 2));
            }
            float al[4];
            #pragma unroll
            for (int i = 0; i < 4; i++) {
                const float mn = fmaxf(mrun[i], m[i]);
                al[i] = fast_exp2(mrun[i] - mn);
                mrun[i] = mn;
            }
            float l[4] = {0.0f, 0.0f, 0.0f, 0.0f};
            #pragma unroll
            for (int jq = 0; jq < 2; jq++)
                #pragma unroll
                for (int i = 0; i < 4; i++) {
                    sacc[jq][2 * i]     = fast_exp2(sacc[jq][2 * i]     - mrun[i]);
                    sacc[jq][2 * i + 1] = fast_exp2(sacc[jq][2 * i + 1] - mrun[i]);
                    l[i] += sacc[jq][2 * i] + sacc[jq][2 * i + 1];
                }
            #pragma unroll
            for (int i = 0; i < 4; i++) {
                l[i] += __shfl_xor_sync(0xffffffffu, l[i], 1);
                l[i] += __shfl_xor_sync(0xffffffffu, l[i], 2);
                lrun[i] = lrun[i] * al[i] + l[i];
            }

            // rescale O (fma pipe; waits on prev PV via scoreboard)
            #pragma unroll
            for (int j = 0; j < 8; j++)
                #pragma unroll
                for (int i = 0; i < 4; i++) {
                    o[j][2 * i]     *= al[i];
                    o[j][2 * i + 1] *= al[i];
                }

            // store P quarter, transposed pad: PPU[col][row], col = jq*8+2b+par
            #pragma unroll
            for (int jq = 0; jq < 2; jq++) {
                #pragma unroll
                for (int rb = 0; rb < 4; rb++) {
                    const int rowi = prow + 8 * rb;
                    PPU[(jq * 8 + 2 * b)     * PST + rowi] = f2tf(sacc[jq][2 * rb]);
                    PPU[(jq * 8 + 2 * b + 1) * PST + rowi] = f2tf(sacc[jq][2 * rb + 1]);
                }
            }
            __syncwarp();  // warp-private rows: publish P before A-frag loads

            // PV quarter: O += P(:, q*16..+15) @ V(q*16..+15, :)
            #pragma unroll
            for (int kcl = 0; kcl < 2; kcl++) {
                uint32_t pa0[4], pa1[4];
                const int c0 = (kcl * 8 + b) * PST + prow;
                const int c4 = (kcl * 8 + b + 4) * PST + prow;
                pa0[0] = PPU[c0];      pa0[1] = PPU[c0 + 8];
                pa0[2] = PPU[c4];      pa0[3] = PPU[c4 + 8];
                pa1[0] = PPU[c0 + 16]; pa1[1] = PPU[c0 + 24];
                pa1[2] = PPU[c4 + 16]; pa1[3] = PPU[c4 + 24];
                const int vr0 = (q * 16 + kcl * 8 + b) * VSS;
                const int vr1 = (q * 16 + kcl * 8 + b + 4) * VSS;
                #pragma unroll
                for (int j = 0; j < 8; j++) {
                    const uint32_t v0 = VsU[vr0 + j * 8 + g];
                    const uint32_t v1 = VsU[vr1 + j * 8 + g];
                    mma_tf32(&o[j][0], pa0, v0, v1);
                    mma_tf32(&o[j][4], pa1, v0, v1);
                }
            }
            __syncwarp();  // P reads done before next quarter overwrites pad
        }

        __syncthreads();  // all K(it)/V(it) reads done before refills

        // ---- issue V(it+1) and K(it+2) (clamped tail keeps group pattern) ----
        if (it + 1 < NITER) {
            const int vnx = (it + 1) * BK;
            #pragma unroll
            for (int i = 0; i < 8; i++) {
                const int r = srow + 8 * i;
                cp16(sb + (VOFF + r * VSS + scol) * 4, vg + (size_t)(vnx + r) * DIM + scol);
            }
            CP_COMMIT();
            const int knx = (it + 2 < NITER ? it + 2 : NITER - 1) * BK;
            const uint32_t kdst = sb + ((it & 1) ? KST1 : KST0) * 4;
            #pragma unroll
            for (int i = 0; i < 8; i++) {
                const int r = srow + 8 * i;
                cp16(kdst + (r * KSS + scol) * 4, kg + (size_t)(knx + r) * DIM + scol);
            }
            CP_COMMIT();
        }
    }

    // ---- epilogue: normalize + store ----
    {
        float inv[4];
        #pragma unroll
        for (int i = 0; i < 4; i++) inv[i] = (lrun[i] > 0.0f) ? (1.0f / lrun[i]) : 0.0f;
        float* orow = out + ((size_t)head * QLEN + q0 + r0) * DIM;
        #pragma unroll
        for (int j = 0; j < 8; j++) {
            const int col = j * 8 + 2 * b;
            *(float2*)&orow[ 0 * DIM + col] = make_float2(o[j][0] * inv[0], o[j][1] * inv[0]);
            *(float2*)&orow[ 8 * DIM + col] = make_float2(o[j][2] * inv[1], o[j][3] * inv[1]);
            *(float2*)&orow[16 * DIM + col] = make_float2(o[j][4] * inv[2], o[j][5] * inv[2]);
            *(float2*)&orow[24 * DIM + col] = make_float2(o[j][6] * inv[3], o[j][7] * inv[3]);
        }
    }
}

extern "C" void kernel_launch(void* const* d_in, const int* in_sizes, int n_in,
                              void* d_out, int out_size)
{
    const float* qs = (const float*)d_in[0];
    const float* ks = (const float*)d_in[1];
    const float* vs = (const float*)d_in[2];
    const unsigned int* maskw = (const unsigned int*)d_in[3];
    float* out = (float*)d_out;

    const int total4 = NHEAD * KLEN * DIM / 4;
    kv_round<<<total4 / 256, 256>>>(ks, vs);

    cudaFuncSetAttribute(fa_hmma_q4, cudaFuncAttributeMaxDynamicSharedMemorySize, SMEM_BYTES);
    dim3 grid(QLEN / BQ, NHEAD);
    fa_hmma_q4<<<grid, NTHREADS, SMEM_BYTES>>>(qs, maskw, out);
}

// round 9
// speedup vs baseline: 1.2328x; 1.2328x over previous
#include <cuda_runtime.h>
#include <cstdint>

#define NHEAD 16
#define QLEN  4096
#define KLEN  4096
#define DIM   64
#define BQ    128
#define BK    64
#define NTHREADS 128
#define NITER (KLEN / BK)

#define QTS 132  // Q_T stride: A-frag LDS bank = 4b+g (conflict-free)
#define KSS 68   // K tile stride: B-frag bank = 4g+b (CF)
#define VSS 72   // V tile stride: B-frag bank = 8b+g (CF)
#define PST 132  // P pad (transposed [col][row]): stores 8b+g, loads 4b+g (CF)

// float offsets in dynamic smem
#define QOFF 0
#define KST0 (64 * QTS)                    // 8448
#define KST1 (KST0 + 64 * KSS)             // 12800
#define VOFF (KST1 + 64 * KSS)             // 17152
#define POFF (VOFF + 64 * VSS)             // 21760
#define SMEM_FLOATS (POFF + 32 * PST)      // 25984
#define SMEM_BYTES  (SMEM_FLOATS * 4)      // 103936

// pre-rounded tf32 K/V scratch (static __device__: allocation-free)
__device__ uint32_t g_Kr[NHEAD * KLEN * DIM];
__device__ uint32_t g_Vr[NHEAD * KLEN * DIM];

__device__ __forceinline__ uint32_t f2tf(float x) {
    uint32_t r; asm("cvt.rna.tf32.f32 %0, %1;" : "=r"(r) : "f"(x)); return r;
}
__device__ __forceinline__ float fast_exp2(float x) {
    float y; asm("ex2.approx.ftz.f32 %0, %1;" : "=f"(y) : "f"(x)); return y;
}
__device__ __forceinline__ uint32_t smem_u32(const void* p) {
    uint32_t a;
    asm("{ .reg .u64 t; cvta.to.shared.u64 t, %1; cvt.u32.u64 %0, t; }" : "=r"(a) : "l"(p));
    return a;
}
__device__ __forceinline__ void cp16(uint32_t dst, const void* src) {
    asm volatile("cp.async.ca.shared.global [%0], [%1], 16;" :: "r"(dst), "l"(src) : "memory");
}
#define CP_COMMIT() asm volatile("cp.async.commit_group;" ::: "memory")
#define CP_WAIT0()  asm volatile("cp.async.wait_group 0;" ::: "memory")
#define CP_WAIT1()  asm volatile("cp.async.wait_group 1;" ::: "memory")

// D(16x8,f32) += A(16x8,tf32) * B(8x8,tf32)   [row.col]
__device__ __forceinline__ void mma_tf32(float* d, const uint32_t* a,
                                         uint32_t b0, uint32_t b1) {
    asm volatile(
        "mma.sync.aligned.m16n8k8.row.col.f32.tf32.tf32.f32 "
        "{%0,%1,%2,%3}, {%4,%5,%6,%7}, {%8,%9}, {%0,%1,%2,%3};"
        : "+f"(d[0]), "+f"(d[1]), "+f"(d[2]), "+f"(d[3])
        : "r"(a[0]), "r"(a[1]), "r"(a[2]), "r"(a[3]), "r"(b0), "r"(b1));
}

// ---- prepass: round K,V to tf32 (rna) once ----
extern "C" __global__ void __launch_bounds__(256)
kv_round(const float* __restrict__ ks, const float* __restrict__ vs)
{
    const size_t i = (size_t)blockIdx.x * blockDim.x + threadIdx.x;
    float4 k = ((const float4*)ks)[i];
    ((uint4*)g_Kr)[i] = make_uint4(f2tf(k.x), f2tf(k.y), f2tf(k.z), f2tf(k.w));
    float4 v = ((const float4*)vs)[i];
    ((uint4*)g_Vr)[i] = make_uint4(f2tf(v.x), f2tf(v.y), f2tf(v.z), f2tf(v.w));
}

// MMA1: S = Q_tile @ K_tile^T, Q A-frags from smem Q_T, result into nxt
__device__ __forceinline__ void mma1_block(float (&nxt)[8][8],
                                           const uint32_t* __restrict__ KsU,
                                           const uint32_t* __restrict__ QT,
                                           int r0, int g, int b)
{
    #pragma unroll
    for (int j = 0; j < 8; j++)
        #pragma unroll
        for (int e = 0; e < 8; e++) nxt[j][e] = 0.0f;

    #pragma unroll
    for (int c = 0; c < 8; c++) {
        uint32_t a0[4], a1[4];
        const uint32_t* q0 = &QT[(c * 8 + b) * QTS + r0];
        const uint32_t* q4 = &QT[(c * 8 + b + 4) * QTS + r0];
        a0[0] = q0[0];  a0[1] = q0[8];  a0[2] = q4[0];  a0[3] = q4[8];
        a1[0] = q0[16]; a1[1] = q0[24]; a1[2] = q4[16]; a1[3] = q4[24];
        #pragma unroll
        for (int j = 0; j < 8; j++) {
            const uint32_t* kp = &KsU[(j * 8 + g) * KSS + c * 8 + b];
            const uint32_t kb0 = kp[0], kb1 = kp[4];
            mma_tf32(&nxt[j][0], a0, kb0, kb1);
            mma_tf32(&nxt[j][4], a1, kb0, kb1);
        }
    }
}

extern "C" __global__ void __launch_bounds__(NTHREADS, 2)
fa_hmma_pipe(const float* __restrict__ qs, const unsigned int* __restrict__ maskw,
             float* __restrict__ out)
{
    extern __shared__ float sm[];
    const uint32_t sb = smem_u32(sm);

    const int tid  = threadIdx.x;
    const int w    = tid >> 5;
    const int lane = tid & 31;
    const int g    = lane >> 2;
    const int b    = lane & 3;

    uint32_t* QT  = (uint32_t*)(sm + QOFF);
    uint32_t* PPU = (uint32_t*)(sm + POFF);
    const int prow = w * 32 + g;
    const int r0   = w * 32 + g;

    const int head = blockIdx.y;
    const int q0   = blockIdx.x * BQ;

    const float qscale = 0.125f * 1.44269504088896340736f;  // 1/sqrt(D)*log2(e)
    const float* qg = qs + ((size_t)head * QLEN + q0) * DIM;
    const uint32_t* kg = g_Kr + (size_t)head * KLEN * DIM;
    const uint32_t* vg = g_Vr + (size_t)head * KLEN * DIM;

    const int srow = tid >> 4;          // cp.async row base (0..7)
    const int scol = (tid & 15) * 4;    // cp.async col (floats)

    // ---- prologue: issue G0={K(0),V(0)}, G1={K(1)} ----
    #pragma unroll
    for (int i = 0; i < 8; i++) {
        const int r = srow + 8 * i;
        cp16(sb + (KST0 + r * KSS + scol) * 4, kg + (size_t)r * DIM + scol);
        cp16(sb + (VOFF + r * VSS + scol) * 4, vg + (size_t)r * DIM + scol);
    }
    CP_COMMIT();
    #pragma unroll
    for (int i = 0; i < 8; i++) {
        const int r = srow + 8 * i;
        cp16(sb + (KST1 + r * KSS + scol) * 4, kg + (size_t)(BK + r) * DIM + scol);
    }
    CP_COMMIT();

    // ---- stage Q transposed (scaled, tf32-rounded) while cp.async flies ----
    #pragma unroll
    for (int i = 0; i < 16; i++) {
        const int idx = tid + NTHREADS * i;
        const int r = idx >> 4, c4 = (idx & 15) * 4;
        float4 v = *(const float4*)(qg + (size_t)r * DIM + c4);
        QT[(c4 + 0) * QTS + r] = f2tf(v.x * qscale);
        QT[(c4 + 1) * QTS + r] = f2tf(v.y * qscale);
        QT[(c4 + 2) * QTS + r] = f2tf(v.z * qscale);
        QT[(c4 + 3) * QTS + r] = f2tf(v.w * qscale);
    }

    float o[8][8];
    #pragma unroll
    for (int j = 0; j < 8; j++)
        #pragma unroll
        for (int e = 0; e < 8; e++) o[j][e] = 0.0f;
    float mrun[4] = {-1e30f, -1e30f, -1e30f, -1e30f};
    float lrun[4] = {0.0f, 0.0f, 0.0f, 0.0f};

    float sA[8][8], sB[8][8];

    // G0 landed (K0,V0); G1 (K1) may fly. Q_T stores need the barrier too.
    CP_WAIT1();
    __syncthreads();
    mma1_block(sA, (const uint32_t*)(sm + KST0), QT, r0, g, b);

    // ---- iteration body (cur = S(it), nxt <- S(it+1)) ----
    auto iter_body = [&](int it, float (&cur)[8][8], float (&nxt)[8][8]) {
        const int kb = (it * BK) >> 2;

        CP_WAIT0();          // K(it+1) and V(it) landed
        __syncthreads();     // cross-thread visibility; prev-iter smem reads done

        // MMA1(it+1): fills tensor queue; independent of cur
        if (it + 1 < NITER)
            mma1_block(nxt, (const uint32_t*)(sm + (((it + 1) & 1) ? KST1 : KST0)),
                       QT, r0, g, b);

        // prefetch K(it+2) into the stage MMA1(it) used last iteration
        {
            const int knx = (it + 2 < NITER ? it + 2 : NITER - 1) * BK;
            const uint32_t kdst = sb + ((it & 1) ? KST1 : KST0) * 4;
            #pragma unroll
            for (int i = 0; i < 8; i++) {
                const int r = srow + 8 * i;
                cp16(kdst + (r * KSS + scol) * 4, kg + (size_t)(knx + r) * DIM + scol);
            }
            CP_COMMIT();
        }

        // ---- mask + online softmax on cur (whole 64-key block) ----
        #pragma unroll
        for (int j = 0; j < 8; j++) {
            if (maskw[kb + 2 * j + (b >> 1)] == 0u) {
                #pragma unroll
                for (int e = 0; e < 8; e++) cur[j][e] = -1e30f;
            }
        }
        float m[4] = {-1e30f, -1e30f, -1e30f, -1e30f};
        #pragma unroll
        for (int j = 0; j < 8; j++)
            #pragma unroll
            for (int i = 0; i < 4; i++)
                m[i] = fmaxf(m[i], fmaxf(cur[j][2 * i], cur[j][2 * i + 1]));
        #pragma unroll
        for (int i = 0; i < 4; i++) {
            m[i] = fmaxf(m[i], __shfl_xor_sync(0xffffffffu, m[i], 1));
            m[i] = fmaxf(m[i], __shfl_xor_sync(0xffffffffu, m[i], 2));
        }
        float al[4];
        #pragma unroll
        for (int i = 0; i < 4; i++) {
            const float mn = fmaxf(mrun[i], m[i]);
            al[i] = fast_exp2(mrun[i] - mn);
            mrun[i] = mn;
        }
        float l[4] = {0.0f, 0.0f, 0.0f, 0.0f};
        #pragma unroll
        for (int j = 0; j < 8; j++)
            #pragma unroll
            for (int i = 0; i < 4; i++) {
                cur[j][2 * i]     = fast_exp2(cur[j][2 * i]     - mrun[i]);
                cur[j][2 * i + 1] = fast_exp2(cur[j][2 * i + 1] - mrun[i]);
                l[i] += cur[j][2 * i] + cur[j][2 * i + 1];
            }
        #pragma unroll
        for (int i = 0; i < 4; i++) {
            l[i] += __shfl_xor_sync(0xffffffffu, l[i], 1);
            l[i] += __shfl_xor_sync(0xffffffffu, l[i], 2);
            lrun[i] = lrun[i] * al[i] + l[i];
        }
        #pragma unroll
        for (int j = 0; j < 8; j++)
            #pragma unroll
            for (int i = 0; i < 4; i++) {
                o[j][2 * i]     *= al[i];
                o[j][2 * i + 1] *= al[i];
            }

        // ---- P + PV in two 32-col halves through the shared transposed pad ----
        #pragma unroll
        for (int h = 0; h < 2; h++) {
            #pragma unroll
            for (int jj = 0; jj < 4; jj++) {
                const int j = h * 4 + jj;
                const int c0 = (jj * 8 + 2 * b) * PST + prow;
                PPU[c0]      = f2tf(cur[j][0]);
                PPU[c0 + 8]  = f2tf(cur[j][2]);
                PPU[c0 + 16] = f2tf(cur[j][4]);
                PPU[c0 + 24] = f2tf(cur[j][6]);
                const int c1 = c0 + PST;
                PPU[c1]      = f2tf(cur[j][1]);
                PPU[c1 + 8]  = f2tf(cur[j][3]);
                PPU[c1 + 16] = f2tf(cur[j][5]);
                PPU[c1 + 24] = f2tf(cur[j][7]);
            }
            __syncwarp();
            const uint32_t* VsU = (const uint32_t*)(sm + VOFF);
            #pragma unroll
            for (int kcl = 0; kcl < 4; kcl++) {
                uint32_t pa0[4], pa1[4];
                const int c0 = (kcl * 8 + b) * PST + prow;
                const int c4 = (kcl * 8 + b + 4) * PST + prow;
                pa0[0] = PPU[c0];      pa0[1] = PPU[c0 + 8];
                pa0[2] = PPU[c4];      pa0[3] = PPU[c4 + 8];
                pa1[0] = PPU[c0 + 16]; pa1[1] = PPU[c0 + 24];
                pa1[2] = PPU[c4 + 16]; pa1[3] = PPU[c4 + 24];
                const int vr0 = (h * 32 + kcl * 8 + b) * VSS;
                const int vr1 = vr0 + 4 * VSS;
                #pragma unroll
                for (int j = 0; j < 8; j++) {
                    const uint32_t v0 = VsU[vr0 + j * 8 + g];
                    const uint32_t v1 = VsU[vr1 + j * 8 + g];
                    mma_tf32(&o[j][0], pa0, v0, v1);
                    mma_tf32(&o[j][4], pa1, v0, v1);
                }
            }
            __syncwarp();
        }

        __syncthreads();   // all V(it) reads done before V(it+1) cp.async

        // prefetch V(it+1) into the single V buffer
        {
            const int vnx = (it + 1 < NITER ? it + 1 : NITER - 1) * BK;
            #pragma unroll
            for (int i = 0; i < 8; i++) {
                const int r = srow + 8 * i;
                cp16(sb + (VOFF + r * VSS + scol) * 4, vg + (size_t)(vnx + r) * DIM + scol);
            }
            CP_COMMIT();
        }
    };

    #pragma unroll 1
    for (int it = 0; it < NITER; it += 2) {
        iter_body(it,     sA, sB);
        iter_body(it + 1, sB, sA);
    }

    // ---- epilogue: normalize + store ----
    {
        float inv[4];
        #pragma unroll
        for (int i = 0; i < 4; i++) inv[i] = (lrun[i] > 0.0f) ? (1.0f / lrun[i]) : 0.0f;
        float* orow = out + ((size_t)head * QLEN + q0 + r0) * DIM;
        #pragma unroll
        for (int j = 0; j < 8; j++) {
            const int col = j * 8 + 2 * b;
            *(float2*)&orow[ 0 * DIM + col] = make_float2(o[j][0] * inv[0], o[j][1] * inv[0]);
            *(float2*)&orow[ 8 * DIM + col] = make_float2(o[j][2] * inv[1], o[j][3] * inv[1]);
            *(float2*)&orow[16 * DIM + col] = make_float2(o[j][4] * inv[2], o[j][5] * inv[2]);
            *(float2*)&orow[24 * DIM + col] = make_float2(o[j][6] * inv[3], o[j][7] * inv[3]);
        }
    }
}

extern "C" void kernel_launch(void* const* d_in, const int* in_sizes, int n_in,
                              void* d_out, int out_size)
{
    const float* qs = (const float*)d_in[0];
    const float* ks = (const float*)d_in[1];
    const float* vs = (const float*)d_in[2];
    const unsigned int* maskw = (const unsigned int*)d_in[3];
    float* out = (float*)d_out;

    const int total4 = NHEAD * KLEN * DIM / 4;
    kv_round<<<total4 / 256, 256>>>(ks, vs);

    cudaFuncSetAttribute(fa_hmma_pipe, cudaFuncAttributeMaxDynamicSharedMemorySize, SMEM_BYTES);
    dim3 grid(QLEN / BQ, NHEAD);
    fa_hmma_pipe<<<grid, NTHREADS, SMEM_BYTES>>>(qs, maskw, out);
}